// round 1
// baseline (speedup 1.0000x reference)
#include <cuda_runtime.h>

// Global double accumulator (scratch via __device__ global — no allocs).
__device__ double g_accum;

__global__ void tv_zero_kernel() { g_accum = 0.0; }

// Fast sqrt: bit-hack rsqrt + 2 Newton iterations (FMA pipe only, no MUFU).
// Max rel err ~5e-6. Returns exactly 0 for x == 0.
__device__ __forceinline__ float fsqrt_fast(float x) {
    float xh = 0.5f * x;
    float r = __uint_as_float(0x5f3759dfu - (__float_as_uint(x) >> 1));
    r = r * (1.5f - xh * r * r);
    r = r * (1.5f - xh * r * r);
    return x * r;
}

// Shapes fixed by the problem: [8,3,16,256,256] fp32. H = W = 256.
// Row = 64 float4. Each thread handles 4 consecutive float4 (16 elems) of one row.
__global__ void __launch_bounds__(256) tv_main_kernel(const float4* __restrict__ in4) {
    const int t  = blockIdx.x * 256 + threadIdx.x;
    const int q0 = t << 2;            // first float4 index (aligned to 4, same row)
    const int r  = q0 >> 6;           // global row id (plane*256 + h)
    const int w4 = q0 & 63;           // float4 offset within row
    const int h  = r & 255;
    const int plane = r >> 8;
    const int rowbase = r << 6;
    const int dbase   = ((plane << 8) | ((h + 1) & 255)) << 6;  // circular down row

    const float4 a0 = in4[rowbase + w4];
    const float4 a1 = in4[rowbase + w4 + 1];
    const float4 a2 = in4[rowbase + w4 + 2];
    const float4 a3 = in4[rowbase + w4 + 3];
    const float4 b  = in4[rowbase + ((w4 + 4) & 63)];           // circular right wrap
    const float4 c0 = in4[dbase + w4];
    const float4 c1 = in4[dbase + w4 + 1];
    const float4 c2 = in4[dbase + w4 + 2];
    const float4 c3 = in4[dbase + w4 + 3];

    float acc = 0.0f;
    #define TV_PROC(a, nx, c)                                              \
    {                                                                      \
        float dx0 = a.x - a.y,  dy0 = a.x - c.x;                           \
        float dx1 = a.y - a.z,  dy1 = a.y - c.y;                           \
        float dx2 = a.z - a.w,  dy2 = a.z - c.z;                           \
        float dx3 = a.w - (nx), dy3 = a.w - c.w;                           \
        acc += fsqrt_fast(fmaf(dx0, dx0, dy0 * dy0));                      \
        acc += fsqrt_fast(fmaf(dx1, dx1, dy1 * dy1));                      \
        acc += fsqrt_fast(fmaf(dx2, dx2, dy2 * dy2));                      \
        acc += fsqrt_fast(fmaf(dx3, dx3, dy3 * dy3));                      \
    }
    TV_PROC(a0, a1.x, c0)
    TV_PROC(a1, a2.x, c1)
    TV_PROC(a2, a3.x, c2)
    TV_PROC(a3, b.x,  c3)
    #undef TV_PROC

    // Warp reduce
    #pragma unroll
    for (int o = 16; o > 0; o >>= 1)
        acc += __shfl_xor_sync(0xFFFFFFFFu, acc, o);

    __shared__ float warpsum[8];
    const int lane = threadIdx.x & 31;
    const int wid  = threadIdx.x >> 5;
    if (lane == 0) warpsum[wid] = acc;
    __syncthreads();

    if (wid == 0) {
        float s = (lane < 8) ? warpsum[lane] : 0.0f;
        #pragma unroll
        for (int o = 4; o > 0; o >>= 1)
            s += __shfl_xor_sync(0xFFFFFFFFu, s, o);
        if (lane == 0) atomicAdd(&g_accum, (double)s);
    }
}

__global__ void tv_fin_kernel(float* __restrict__ out, double inv_n) {
    out[0] = (float)(g_accum * inv_n);
}

extern "C" void kernel_launch(void* const* d_in, const int* in_sizes, int n_in,
                              void* d_out, int out_size) {
    const float4* in4 = (const float4*)d_in[0];
    float* out = (float*)d_out;
    const long long n = in_sizes[0];              // 25,165,824
    const int elems_per_thread = 16;
    const int threads = 256;
    const int blocks = (int)(n / (threads * elems_per_thread));  // 6144

    tv_zero_kernel<<<1, 1>>>();
    tv_main_kernel<<<blocks, threads>>>(in4);
    tv_fin_kernel<<<1, 1>>>(out, 1.0 / (double)n);
}